// round 2
// baseline (speedup 1.0000x reference)
#include <cuda_runtime.h>
#include <math.h>

// ---------------- problem constants ----------------
#define BB   512
#define TT   256
#define CC   256
#define MTOT (BB*TT)        // 131072
#define HH   4
#define DH   64
#define KC   16
#define KMI  10
#define EPSF 1e-8f

// ---------------- scratch (static device globals; no allocation) ------------
__device__ float g_X  [(size_t)MTOT*CC];
__device__ float g_B1 [(size_t)MTOT*CC];   // qin / f / final-LN out
__device__ float g_Q  [(size_t)MTOT*CC];   // also reused as FFN hidden
__device__ float g_K  [(size_t)MTOT*CC];
__device__ float g_V  [(size_t)MTOT*CC];
__device__ float g_ATT[(size_t)MTOT*CC];
__device__ int   g_ids[MTOT];

// ---------------- embed: x = concat(item[seq], user[uid]) + pos_emb --------
__global__ void __launch_bounds__(256) embed_kernel(
    const int* __restrict__ uid, const int* __restrict__ seq,
    const float* __restrict__ item, const float* __restrict__ user,
    const float* __restrict__ pos, float* __restrict__ X)
{
    int i = blockIdx.x * 256 + threadIdx.x;          // one float4 per thread
    if (i >= MTOT * 64) return;
    int bt = i >> 6;
    int c  = (i & 63) << 2;
    int t  = bt & 255;
    int b  = bt >> 8;
    float4 e;
    if (c < 192) e = *(const float4*)(item + (size_t)seq[bt] * 192 + c);
    else         e = *(const float4*)(user + (size_t)uid[b] * 64 + (c - 192));
    float4 p = *(const float4*)(pos + t * 256 + c);
    e.x += p.x; e.y += p.y; e.z += p.z; e.w += p.w;
    *(float4*)(X + (size_t)bt * 256 + c) = e;
}

// ---------------- mask: x *= (seq != 0) ------------------------------------
__global__ void __launch_bounds__(256) mask_kernel(
    float* __restrict__ X, const int* __restrict__ seq)
{
    int i = blockIdx.x * 256 + threadIdx.x;
    if (i >= MTOT * 64) return;
    int bt = i >> 6;
    if (seq[bt] == 0) {
        int c = (i & 63) << 2;
        *(float4*)(X + (size_t)bt * 256 + c) = make_float4(0.f, 0.f, 0.f, 0.f);
    }
}

// ---------------- k-means: one block per batch -----------------------------
__global__ void __launch_bounds__(256) kmeans_kernel(
    const float* __restrict__ Xall, int* __restrict__ idsall)
{
    __shared__ float cent[KC][CC];       // 16 KB
    __shared__ float sums[CC * 17];      // [c][k] stride 17 (conflict-free)
    __shared__ float xsq[TT];
    __shared__ float csq[KC];
    __shared__ float cnt[KC];
    __shared__ int   ids[TT];

    int b = blockIdx.x, tid = threadIdx.x;
    const float* X = Xall + (size_t)b * TT * CC;

    // init centroids = first 16 rows
    for (int i = tid; i < KC * CC; i += 256) cent[i >> 8][i & 255] = X[i];
    // x squared norms
    {
        float s = 0.f;
        const float4* xr = (const float4*)(X + (size_t)tid * CC);
        #pragma unroll 8
        for (int j = 0; j < 64; j++) {
            float4 v = xr[j];
            s += v.x*v.x + v.y*v.y + v.z*v.z + v.w*v.w;
        }
        xsq[tid] = s;
    }
    __syncthreads();

    for (int iter = 0; iter <= KMI; iter++) {
        if (tid < KC) {
            float s = 0.f;
            for (int c = 0; c < CC; c++) { float v = cent[tid][c]; s += v * v; }
            csq[tid] = s;
        }
        __syncthreads();

        // assignment
        float dot[KC];
        #pragma unroll
        for (int k = 0; k < KC; k++) dot[k] = 0.f;
        {
            const float4* xr = (const float4*)(X + (size_t)tid * CC);
            #pragma unroll 4
            for (int j = 0; j < 64; j++) {
                float4 xv = xr[j];
                #pragma unroll
                for (int k = 0; k < KC; k++) {
                    float4 cv = ((const float4*)cent[k])[j];
                    dot[k] += xv.x*cv.x + xv.y*cv.y + xv.z*cv.z + xv.w*cv.w;
                }
            }
        }
        int best = 0;
        float bd = xsq[tid] - 2.f * dot[0] + csq[0];
        #pragma unroll
        for (int k = 1; k < KC; k++) {
            float d = xsq[tid] - 2.f * dot[k] + csq[k];
            if (d < bd) { bd = d; best = k; }   // first-min, matches argmin
        }
        ids[tid] = best;

        if (iter == KMI) {            // final assignment -> global
            idsall[b * TT + tid] = best;
        } else {
            __syncthreads();
            // zero accumulators
            for (int i = tid; i < CC * 17; i += 256) sums[i] = 0.f;
            __syncthreads();
            if (tid < KC) {
                float c = 0.f;
                for (int t = 0; t < TT; t++) c += (ids[t] == tid) ? 1.f : 0.f;
                cnt[tid] = c;
            }
            {   // per-dim accumulation: thread = dim c
                float* srow = sums + tid * 17;
                for (int t = 0; t < TT; t++) {
                    float v = X[(size_t)t * CC + tid];     // coalesced
                    srow[ids[t]] += v;
                }
            }
            __syncthreads();
            for (int i = tid; i < KC * CC; i += 256) {
                int k = i >> 8, c = i & 255;
                float ct = cnt[k];
                if (ct > 0.f) cent[k][c] = sums[c * 17 + k] / ct;
            }
            __syncthreads();
        }
    }
}

// ---------------- layer norm (warp per row, biased var) --------------------
__global__ void __launch_bounds__(256) ln_kernel(
    const float* __restrict__ X, float* __restrict__ Y,
    const float* __restrict__ g, const float* __restrict__ bb)
{
    int row  = (blockIdx.x << 3) + (threadIdx.x >> 5);
    int lane = threadIdx.x & 31;
    const float* xr = X + (size_t)row * CC + lane * 8;
    float4 a = *(const float4*)xr;
    float4 c = *(const float4*)(xr + 4);
    float s = a.x + a.y + a.z + a.w + c.x + c.y + c.z + c.w;
    #pragma unroll
    for (int o = 16; o; o >>= 1) s += __shfl_xor_sync(0xffffffffu, s, o);
    float mu = s * (1.f / 256.f);
    float d0 = a.x - mu, d1 = a.y - mu, d2 = a.z - mu, d3 = a.w - mu;
    float d4 = c.x - mu, d5 = c.y - mu, d6 = c.z - mu, d7 = c.w - mu;
    float vs = d0*d0 + d1*d1 + d2*d2 + d3*d3 + d4*d4 + d5*d5 + d6*d6 + d7*d7;
    #pragma unroll
    for (int o = 16; o; o >>= 1) vs += __shfl_xor_sync(0xffffffffu, vs, o);
    float var = vs * (1.f / 256.f);
    float rs  = rsqrtf(var + EPSF);
    int col = lane * 8;
    float4 g0 = *(const float4*)(g + col);
    float4 g1 = *(const float4*)(g + col + 4);
    float4 b0 = *(const float4*)(bb + col);
    float4 b1 = *(const float4*)(bb + col + 4);
    float4 o0, o1;
    o0.x = g0.x * d0 * rs + b0.x;  o0.y = g0.y * d1 * rs + b0.y;
    o0.z = g0.z * d2 * rs + b0.z;  o0.w = g0.w * d3 * rs + b0.w;
    o1.x = g1.x * d4 * rs + b1.x;  o1.y = g1.y * d5 * rs + b1.y;
    o1.z = g1.z * d6 * rs + b1.z;  o1.w = g1.w * d7 * rs + b1.w;
    float* yr = Y + (size_t)row * CC + col;
    *(float4*)yr       = o0;
    *(float4*)(yr + 4) = o1;
}

// ---------------- SGEMM: D = epi(A[M,256] @ W[256,256]) --------------------
// tile 128x128x16, 256 threads, 8x8 microtile, DOUBLE-BUFFERED smem pipeline.
__global__ void __launch_bounds__(256) gemm_kernel(
    const float* __restrict__ A, const float* __restrict__ W,
    float* __restrict__ D,
    const float* __restrict__ bias, const float* __restrict__ resid,
    const int* __restrict__ keepseq, int do_relu)
{
    __shared__ float As[2][16][128];
    __shared__ float Bs[2][16][128];
    int tid = threadIdx.x;
    int tx = tid & 15, ty = tid >> 4;
    const float* Ablk = A + (size_t)blockIdx.x * 128 * 256;
    const float* Wblk = W + blockIdx.y * 128;

    // per-thread load coordinates (constant across tiles)
    const int ar0 = tid >> 2,          ac0 = (tid & 3) << 2;          // A part 0
    const int ar1 = (tid + 256) >> 2,  ac1 = ac0;                     // A part 1
    const int wr0 = tid >> 5,          wc0 = (tid & 31) << 2;         // W part 0
    const int wr1 = (tid + 256) >> 5,  wc1 = wc0;                     // W part 1

    float acc[8][8];
    #pragma unroll
    for (int i = 0; i < 8; i++)
        #pragma unroll
        for (int j = 0; j < 8; j++) acc[i][j] = 0.f;

    // prologue: load tile kt=0 into buffer 0
    float4 av0 = *(const float4*)(Ablk + (size_t)ar0 * 256 + ac0);
    float4 av1 = *(const float4*)(Ablk + (size_t)ar1 * 256 + ac1);
    float4 wv0 = *(const float4*)(Wblk + (size_t)wr0 * 256 + wc0);
    float4 wv1 = *(const float4*)(Wblk + (size_t)wr1 * 256 + wc1);
    As[0][ac0+0][ar0] = av0.x; As[0][ac0+1][ar0] = av0.y;
    As[0][ac0+2][ar0] = av0.z; As[0][ac0+3][ar0] = av0.w;
    As[0][ac1+0][ar1] = av1.x; As[0][ac1+1][ar1] = av1.y;
    As[0][ac1+2][ar1] = av1.z; As[0][ac1+3][ar1] = av1.w;
    *(float4*)&Bs[0][wr0][wc0] = wv0;
    *(float4*)&Bs[0][wr1][wc1] = wv1;
    __syncthreads();

    int buf = 0;
    #pragma unroll 1
    for (int kt = 0; kt < 256; kt += 16) {
        // prefetch next tile into registers (no smem touch yet)
        if (kt + 16 < 256) {
            const float* An = Ablk + kt + 16;
            const float* Wn = Wblk + (size_t)(kt + 16) * 256;
            av0 = *(const float4*)(An + (size_t)ar0 * 256 + ac0);
            av1 = *(const float4*)(An + (size_t)ar1 * 256 + ac1);
            wv0 = *(const float4*)(Wn + (size_t)wr0 * 256 + wc0);
            wv1 = *(const float4*)(Wn + (size_t)wr1 * 256 + wc1);
        }
        // compute on current buffer
        #pragma unroll
        for (int kk = 0; kk < 16; kk++) {
            float a[8], bfr[8];
            float4 a0 = *(const float4*)&As[buf][kk][ty * 8];
            float4 a1 = *(const float4*)&As[buf][kk][ty * 8 + 4];
            float4 b0 = *(const float4*)&Bs[buf][kk][tx * 8];
            float4 b1 = *(const float4*)&Bs[buf][kk][tx * 8 + 4];
            a[0]=a0.x; a[1]=a0.y; a[2]=a0.z; a[3]=a0.w;
            a[4]=a1.x; a[5]=a1.y; a[6]=a1.z; a[7]=a1.w;
            bfr[0]=b0.x; bfr[1]=b0.y; bfr[2]=b0.z; bfr[3]=b0.w;
            bfr[4]=b1.x; bfr[5]=b1.y; bfr[6]=b1.z; bfr[7]=b1.w;
            #pragma unroll
            for (int i = 0; i < 8; i++)
                #pragma unroll
                for (int j = 0; j < 8; j++)
                    acc[i][j] = fmaf(a[i], bfr[j], acc[i][j]);
        }
        // store prefetched tile into other buffer
        if (kt + 16 < 256) {
            int nb = buf ^ 1;
            As[nb][ac0+0][ar0] = av0.x; As[nb][ac0+1][ar0] = av0.y;
            As[nb][ac0+2][ar0] = av0.z; As[nb][ac0+3][ar0] = av0.w;
            As[nb][ac1+0][ar1] = av1.x; As[nb][ac1+1][ar1] = av1.y;
            As[nb][ac1+2][ar1] = av1.z; As[nb][ac1+3][ar1] = av1.w;
            *(float4*)&Bs[nb][wr0][wc0] = wv0;
            *(float4*)&Bs[nb][wr1][wc1] = wv1;
            __syncthreads();
            buf = nb;
        }
    }

    // epilogue
    #pragma unroll
    for (int i = 0; i < 8; i++) {
        int m = blockIdx.x * 128 + ty * 8 + i;
        float keep = 1.f;
        if (keepseq) keep = (keepseq[m] != 0) ? 1.f : 0.f;
        #pragma unroll
        for (int j = 0; j < 8; j++) {
            int n = blockIdx.y * 128 + tx * 8 + j;
            float v = acc[i][j];
            if (bias) v += bias[n];
            if (do_relu) v = fmaxf(v, 0.f);
            if (resid) v += resid[(size_t)m * 256 + n];
            v *= keep;
            acc[i][j] = v;
        }
        float* dr = D + (size_t)m * 256 + blockIdx.y * 128 + tx * 8;
        *(float4*)dr       = make_float4(acc[i][0], acc[i][1], acc[i][2], acc[i][3]);
        *(float4*)(dr + 4) = make_float4(acc[i][4], acc[i][5], acc[i][6], acc[i][7]);
    }
}

// ---------------- fused cluster-masked attention ---------------------------
// block = (b,h), thread = q-row. Online softmax, K/V staged in 64-row tiles.
__global__ void __launch_bounds__(256, 1) attn_kernel(
    const float* __restrict__ Q, const float* __restrict__ K,
    const float* __restrict__ V, const int* __restrict__ ids,
    const int* __restrict__ seq, float* __restrict__ O)
{
    __shared__ float Ks[64][64];
    __shared__ float Vs[64][64];
    __shared__ int   cids[256];
    int b = blockIdx.x, h = blockIdx.y;
    int tid = threadIdx.x;                 // q row
    cids[tid] = ids[b * 256 + tid];
    bool qpad = (seq[b * 256 + tid] == 0);

    float qreg[64];
    {
        const float* qr = Q + ((size_t)b * 256 + tid) * 256 + h * 64;
        #pragma unroll
        for (int j = 0; j < 16; j++) {
            float4 v = *(const float4*)(qr + 4 * j);
            qreg[4*j] = v.x; qreg[4*j+1] = v.y; qreg[4*j+2] = v.z; qreg[4*j+3] = v.w;
        }
    }
    float m = -INFINITY, l = 0.f;
    float accum[64];
    #pragma unroll
    for (int d = 0; d < 64; d++) accum[d] = 0.f;
    __syncthreads();
    int myid = cids[tid];

    for (int k0 = 0; k0 < 256; k0 += 64) {
        __syncthreads();
        #pragma unroll
        for (int i = 0; i < 4; i++) {      // 64x64 floats = 1024 float4 per tile
            int f = tid + i * 256;
            int r = f >> 4;
            int c = (f & 15) << 2;
            size_t gidx = ((size_t)b * 256 + k0 + r) * 256 + h * 64 + c;
            *(float4*)&Ks[r][c] = *(const float4*)(K + gidx);
            *(float4*)&Vs[r][c] = *(const float4*)(V + gidx);
        }
        __syncthreads();
        for (int kk = 0; kk < 64; kk++) {
            bool allowed = (cids[k0 + kk] == myid) && !qpad;
            float d0 = 0.f, d1 = 0.f, d2 = 0.f, d3 = 0.f;
            const float4* kr = (const float4*)Ks[kk];
            #pragma unroll
            for (int j = 0; j < 16; j += 4) {
                float4 v0 = kr[j+0], v1 = kr[j+1], v2 = kr[j+2], v3 = kr[j+3];
                d0 = fmaf(qreg[4*j+0],  v0.x, d0); d0 = fmaf(qreg[4*j+1],  v0.y, d0);
                d0 = fmaf(qreg[4*j+2],  v0.z, d0); d0 = fmaf(qreg[4*j+3],  v0.w, d0);
                d1 = fmaf(qreg[4*j+4],  v1.x, d1); d1 = fmaf(qreg[4*j+5],  v1.y, d1);
                d1 = fmaf(qreg[4*j+6],  v1.z, d1); d1 = fmaf(qreg[4*j+7],  v1.w, d1);
                d2 = fmaf(qreg[4*j+8],  v2.x, d2); d2 = fmaf(qreg[4*j+9],  v2.y, d2);
                d2 = fmaf(qreg[4*j+10], v2.z, d2); d2 = fmaf(qreg[4*j+11], v2.w, d2);
                d3 = fmaf(qreg[4*j+12], v3.x, d3); d3 = fmaf(qreg[4*j+13], v3.y, d3);
                d3 = fmaf(qreg[4*j+14], v3.z, d3); d3 = fmaf(qreg[4*j+15], v3.w, d3);
            }
            float s = allowed ? ((d0 + d1) + (d2 + d3)) * 0.125f : -1e9f;
            if (s > m) {                    // rare after warmup (scores ~0)
                float corr = __expf(m - s);
                l *= corr;
                #pragma unroll
                for (int d = 0; d < 64; d++) accum[d] *= corr;
                m = s;
            }
            float p = __expf(s - m);
            l += p;
            const float4* vr = (const float4*)Vs[kk];
            #pragma unroll
            for (int j = 0; j < 16; j++) {
                float4 v = vr[j];
                accum[4*j+0] = fmaf(p, v.x, accum[4*j+0]);
                accum[4*j+1] = fmaf(p, v.y, accum[4*j+1]);
                accum[4*j+2] = fmaf(p, v.z, accum[4*j+2]);
                accum[4*j+3] = fmaf(p, v.w, accum[4*j+3]);
            }
        }
    }
    float inv = 1.f / l;
    float* orow = O + ((size_t)b * 256 + tid) * 256 + h * 64;
    #pragma unroll
    for (int j = 0; j < 16; j++) {
        *(float4*)(orow + 4 * j) = make_float4(
            accum[4*j+0] * inv, accum[4*j+1] * inv,
            accum[4*j+2] * inv, accum[4*j+3] * inv);
    }
}

// ---------------- logits: warp per (b,t) -----------------------------------
__global__ void __launch_bounds__(256) logits_kernel(
    const float* __restrict__ OUT,
    const int* __restrict__ pseq, const int* __restrict__ nseq,
    const int* __restrict__ uid,
    const float* __restrict__ item, const float* __restrict__ user,
    float* __restrict__ out)
{
    int gw   = (blockIdx.x << 3) + (threadIdx.x >> 5);
    int lane = threadIdx.x & 31;
    int b = gw >> 8;
    int c = lane * 8;
    const float* orow = OUT + (size_t)gw * 256 + c;
    float4 o0 = *(const float4*)orow;
    float4 o1 = *(const float4*)(orow + 4);
    float4 p0, p1, n0, n1;
    if (c < 192) {
        const float* pr = item + (size_t)pseq[gw] * 192 + c;
        const float* nr = item + (size_t)nseq[gw] * 192 + c;
        p0 = *(const float4*)pr; p1 = *(const float4*)(pr + 4);
        n0 = *(const float4*)nr; n1 = *(const float4*)(nr + 4);
    } else {
        const float* ur = user + (size_t)uid[b] * 64 + (c - 192);
        p0 = *(const float4*)ur; p1 = *(const float4*)(ur + 4);
        n0 = p0; n1 = p1;
    }
    float sp = o0.x*p0.x + o0.y*p0.y + o0.z*p0.z + o0.w*p0.w
             + o1.x*p1.x + o1.y*p1.y + o1.z*p1.z + o1.w*p1.w;
    float sn = o0.x*n0.x + o0.y*n0.y + o0.z*n0.z + o0.w*n0.w
             + o1.x*n1.x + o1.y*n1.y + o1.z*n1.z + o1.w*n1.w;
    #pragma unroll
    for (int o = 16; o; o >>= 1) {
        sp += __shfl_xor_sync(0xffffffffu, sp, o);
        sn += __shfl_xor_sync(0xffffffffu, sn, o);
    }
    if (lane == 0) {
        out[gw]        = sp;
        out[MTOT + gw] = sn;
    }
}

// ---------------- launch ----------------------------------------------------
extern "C" void kernel_launch(void* const* d_in, const int* in_sizes, int n_in,
                              void* d_out, int out_size)
{
    const int*   uid   = (const int*)  d_in[0];
    const int*   seq   = (const int*)  d_in[1];
    const int*   pseq  = (const int*)  d_in[2];
    const int*   nseq  = (const int*)  d_in[3];
    const float* item  = (const float*)d_in[4];
    const float* user  = (const float*)d_in[5];
    const float* pemb  = (const float*)d_in[6];
    const float* Wq    = (const float*)d_in[7];
    const float* Wk    = (const float*)d_in[8];
    const float* Wv    = (const float*)d_in[9];
    const float* Wo    = (const float*)d_in[10];
    const float* ln1g  = (const float*)d_in[11];
    const float* ln1b  = (const float*)d_in[12];
    const float* ln2g  = (const float*)d_in[13];
    const float* ln2b  = (const float*)d_in[14];
    const float* W1    = (const float*)d_in[15];
    const float* b1    = (const float*)d_in[16];
    const float* W2    = (const float*)d_in[17];
    const float* b2    = (const float*)d_in[18];
    const float* lnfg  = (const float*)d_in[19];
    const float* lnfb  = (const float*)d_in[20];

    float *X, *B1, *Q, *K, *V, *ATT; int* ids;
    cudaGetSymbolAddress((void**)&X,   g_X);
    cudaGetSymbolAddress((void**)&B1,  g_B1);
    cudaGetSymbolAddress((void**)&Q,   g_Q);
    cudaGetSymbolAddress((void**)&K,   g_K);
    cudaGetSymbolAddress((void**)&V,   g_V);
    cudaGetSymbolAddress((void**)&ATT, g_ATT);
    cudaGetSymbolAddress((void**)&ids, g_ids);

    const int EMB_BLOCKS = (MTOT * 64) / 256;      // 32768
    dim3 ggrid(MTOT / 128, 2);                     // (1024, 2)

    embed_kernel <<<EMB_BLOCKS, 256>>>(uid, seq, item, user, pemb, X);
    kmeans_kernel<<<BB, 256>>>(X, ids);
    mask_kernel  <<<EMB_BLOCKS, 256>>>(X, seq);

    for (int l = 0; l < 2; l++) {
        const size_t wo = (size_t)l * 256 * 256;
        const size_t vo = (size_t)l * 256;
        // q_in = LN1(x)
        ln_kernel<<<MTOT / 8, 256>>>(X, B1, ln1g + vo, ln1b + vo);
        // Q = q_in @ Wq ; K = x @ Wk ; V = x @ Wv
        gemm_kernel<<<ggrid, 256>>>(B1, Wq + wo, Q, nullptr, nullptr, nullptr, 0);
        gemm_kernel<<<ggrid, 256>>>(X,  Wk + wo, K, nullptr, nullptr, nullptr, 0);
        gemm_kernel<<<ggrid, 256>>>(X,  Wv + wo, V, nullptr, nullptr, nullptr, 0);
        // attention (cluster-masked, per-head)
        attn_kernel<<<dim3(BB, HH), 256>>>(Q, K, V, ids, seq, ATT);
        // x = keep * (q_in + attn @ Wo)
        gemm_kernel<<<ggrid, 256>>>(ATT, Wo + wo, X, nullptr, B1, seq, 0);
        // f = LN2(x)
        ln_kernel<<<MTOT / 8, 256>>>(X, B1, ln2g + vo, ln2b + vo);
        // h = relu(f @ W1 + b1)
        gemm_kernel<<<ggrid, 256>>>(B1, W1 + wo, Q, b1 + vo, nullptr, nullptr, 1);
        // x = keep * (x + h @ W2 + b2)
        gemm_kernel<<<ggrid, 256>>>(Q, W2 + wo, X, b2 + vo, X, seq, 0);
    }
    // out = LN_f(x)
    ln_kernel<<<MTOT / 8, 256>>>(X, B1, lnfg, lnfb);
    // pos/neg logits
    logits_kernel<<<MTOT / 8, 256>>>(B1, pseq, nseq, uid, item, user, (float*)d_out);
}